// round 3
// baseline (speedup 1.0000x reference)
#include <cuda_runtime.h>

#define M 8192
// softmax scale = sqrt(1024) = 32
#define LOG2E 1.4426950408889634f

// Scratch (no allocations allowed)
__device__ float g_k[M];
__device__ float g_v[M];

__device__ __forceinline__ float ex2f(float x) {
    float y;
    asm("ex2.approx.ftz.f32 %0, %1;" : "=f"(y) : "f"(x));
    return y;
}

// ---------------------------------------------------------------------------
// Kernel A: k = Wk@x+bk, v = Wv@x+bv.
// Grid: 2 matrices x 1024 groups = 2048 blocks, 256 threads (8 warps).
// Warp-per-row: each warp owns one full 8192-dot-product. No block barriers
// in the mainloop -> pure DRAM streaming of 512 MB.
// ---------------------------------------------------------------------------
__global__ __launch_bounds__(256) void kv_kernel(
    const float* __restrict__ x,
    const float* __restrict__ Wk, const float* __restrict__ bk,
    const float* __restrict__ Wv, const float* __restrict__ bv)
{
    __shared__ float4 xs[M / 4];   // 32 KB

    const int t    = threadIdx.x;
    const int lane = t & 31;
    const int w    = t >> 5;
    const int mat   = blockIdx.x >> 10;     // 0 = K, 1 = V
    const int group = blockIdx.x & 1023;

    const float* W = mat ? Wv : Wk;
    const float* b = mat ? bv : bk;
    float* out     = mat ? g_v : g_k;

    const float4* x4 = (const float4*)x;
    #pragma unroll
    for (int i = 0; i < 8; i++) xs[t + i * 256] = x4[t + i * 256];
    __syncthreads();

    const int row = group * 8 + w;
    const float4* Wrow = (const float4*)(W + (size_t)row * M);

    float acc = 0.0f;
    #pragma unroll 1
    for (int j0 = 0; j0 < 64; j0 += 8) {
        float4 wr[8];
        #pragma unroll
        for (int u = 0; u < 8; u++) wr[u] = Wrow[lane + (j0 + u) * 32];
        #pragma unroll
        for (int u = 0; u < 8; u++) {
            float4 xv = xs[lane + (j0 + u) * 32];
            acc += wr[u].x * xv.x + wr[u].y * xv.y
                 + wr[u].z * xv.z + wr[u].w * xv.w;
        }
    }

    #pragma unroll
    for (int o = 16; o > 0; o >>= 1)
        acc += __shfl_xor_sync(0xffffffffu, acc, o);
    if (lane == 0) out[row] = acc + b[row];
}

// ---------------------------------------------------------------------------
// Kernel B: fused Q matvec + attention.
// Grid: 1024 blocks x 256 threads. Each block:
//   1) q rows base..base+7 via warp-per-row (256 KB of Wq from DRAM)
//   2) block-local k min/max (g_k is L2-hot; ~free)
//   3) out[i] = sum_j exp2(a_i*k_j - m_i)*v_j / sum_j exp2(a_i*k_j - m_i)
// The MUFU.EX2 work overlaps with other blocks' Wq DRAM streaming.
// ---------------------------------------------------------------------------
__global__ __launch_bounds__(256) void qattn_kernel(
    const float* __restrict__ x,
    const float* __restrict__ Wq, const float* __restrict__ bq,
    float* __restrict__ out)
{
    __shared__ float4 xs[M / 4];   // 32 KB
    __shared__ float qv[8];
    __shared__ float redA[8], redB[8];
    __shared__ float s_kmin, s_kmax;

    const int t    = threadIdx.x;
    const int lane = t & 31;
    const int w    = t >> 5;
    const int base = blockIdx.x * 8;

    const float4* x4 = (const float4*)x;
    #pragma unroll
    for (int i = 0; i < 8; i++) xs[t + i * 256] = x4[t + i * 256];
    __syncthreads();

    // --- Phase 1: warp w computes q row base+w ---
    {
        const int row = base + w;
        const float4* Wrow = (const float4*)(Wq + (size_t)row * M);
        float acc = 0.0f;
        #pragma unroll 1
        for (int j0 = 0; j0 < 64; j0 += 8) {
            float4 wr[8];
            #pragma unroll
            for (int u = 0; u < 8; u++) wr[u] = Wrow[lane + (j0 + u) * 32];
            #pragma unroll
            for (int u = 0; u < 8; u++) {
                float4 xv = xs[lane + (j0 + u) * 32];
                acc += wr[u].x * xv.x + wr[u].y * xv.y
                     + wr[u].z * xv.z + wr[u].w * xv.w;
            }
        }
        #pragma unroll
        for (int o = 16; o > 0; o >>= 1)
            acc += __shfl_xor_sync(0xffffffffu, acc, o);
        if (lane == 0) qv[w] = acc + bq[row];
    }

    // --- Phase 2: block-local k min/max (k is fully written by kernel A) ---
    {
        float mn = 1e30f, mx = -1e30f;
        #pragma unroll
        for (int i = 0; i < M / 256; i++) {
            float v = g_k[t + i * 256];
            mn = fminf(mn, v);
            mx = fmaxf(mx, v);
        }
        #pragma unroll
        for (int o = 16; o > 0; o >>= 1) {
            mn = fminf(mn, __shfl_xor_sync(0xffffffffu, mn, o));
            mx = fmaxf(mx, __shfl_xor_sync(0xffffffffu, mx, o));
        }
        if (lane == 0) { redA[w] = mn; redB[w] = mx; }
    }
    __syncthreads();
    if (t == 0) {
        float mn = redA[0], mx = redB[0];
        #pragma unroll
        for (int i = 1; i < 8; i++) {
            mn = fminf(mn, redA[i]);
            mx = fmaxf(mx, redB[i]);
        }
        s_kmin = mn;
        s_kmax = mx;
    }
    __syncthreads();

    // --- Phase 3: attention mainloop (MUFU-bound, 8 rows per (k,v) load) ---
    const float kmin = s_kmin;
    const float kmax = s_kmax;

    float a2[8], nm2[8], S[8], T[8];
    #pragma unroll
    for (int r = 0; r < 8; r++) {
        float a = qv[r] * (LOG2E / 32.0f);           // log2-domain slope
        a2[r]  = a;
        nm2[r] = -((a >= 0.0f) ? a * kmax : a * kmin);
        S[r] = 0.0f;
        T[r] = 0.0f;
    }

    const float4* k4 = (const float4*)g_k;
    const float4* v4 = (const float4*)g_v;

    #pragma unroll
    for (int s = 0; s < 8; s++) {
        const int idx = t + s * 256;
        float4 kq = k4[idx];
        float4 vq = v4[idx];
        #pragma unroll
        for (int c = 0; c < 4; c++) {
            float kc = (&kq.x)[c];
            float vc = (&vq.x)[c];
            #pragma unroll
            for (int r = 0; r < 8; r++) {
                float e = ex2f(fmaf(a2[r], kc, nm2[r]));
                S[r] += e;
                T[r] = fmaf(e, vc, T[r]);
            }
        }
    }

    // --- Phase 4: 8 block reductions of (S, T) ---
    #pragma unroll 1
    for (int r = 0; r < 8; r++) {
        float s = S[r], tt = T[r];
        #pragma unroll
        for (int o = 16; o > 0; o >>= 1) {
            s  += __shfl_xor_sync(0xffffffffu, s, o);
            tt += __shfl_xor_sync(0xffffffffu, tt, o);
        }
        if (lane == 0) { redA[w] = s; redB[w] = tt; }
        __syncthreads();
        if (t == 0) {
            float ss = 0.0f, st = 0.0f;
            #pragma unroll
            for (int i = 0; i < 8; i++) { ss += redA[i]; st += redB[i]; }
            out[base + r] = st / ss;
        }
        __syncthreads();
    }
}

// ---------------------------------------------------------------------------
extern "C" void kernel_launch(void* const* d_in, const int* in_sizes, int n_in,
                              void* d_out, int out_size)
{
    const float* x  = (const float*)d_in[0];
    const float* Wq = (const float*)d_in[1];
    const float* bq = (const float*)d_in[2];
    const float* Wk = (const float*)d_in[3];
    const float* bk = (const float*)d_in[4];
    const float* Wv = (const float*)d_in[5];
    const float* bv = (const float*)d_in[6];
    float* out = (float*)d_out;

    kv_kernel<<<2048, 256>>>(x, Wk, bk, Wv, bv);
    qattn_kernel<<<1024, 256>>>(x, Wq, bq, out);
}